// round 5
// baseline (speedup 1.0000x reference)
#include <cuda_runtime.h>
#include <math.h>

#define Bq   4
#define Sq   2048
#define Dq   512
#define Hq   8
#define DKq  64
#define KN   9
#define BHq  32
#define Mq   8192   /* B*S */
#define EPSN 1e-12f

typedef unsigned long long ull;

// ---------------- packed fp32x2 helpers (sm_103a FFMA2) ----------------
__device__ __forceinline__ ull pack2(float x) {
    ull r;
    asm("mov.b64 %0, {%1, %1};" : "=l"(r) : "f"(x));
    return r;
}
__device__ __forceinline__ void fma2(ull& d, ull a, ull b) {
    asm("fma.rn.f32x2 %0, %1, %2, %0;" : "+l"(d) : "l"(a), "l"(b));
}
__device__ __forceinline__ float lo32(ull v) {
    return __uint_as_float((unsigned)v);
}
__device__ __forceinline__ float hi32(ull v) {
    return __uint_as_float((unsigned)(v >> 32));
}

// ---------------- scratch (device globals; no allocation) ----------------
__device__ float g_q[BHq * Sq * DKq];      // [bh][s][c]
__device__ float g_k[BHq * Sq * DKq];
__device__ float g_v[BHq * Sq * DKq];
__device__ int   g_idx[BHq * Sq * KN];     // top-9 indices, sorted desc by sim
__device__ float g_y[Dq * Mq];             // y^T: [col][b*S + s']
__device__ float g_wt[KN * DKq * DKq];     // Wt[kk][c][o]

// ---------------- Kernel A: QKV GEMM  out = x @ W^T + b, split-head layout ----
// B operand pre-duplicated in smem (ull per value); cols per thread strided.
__global__ __launch_bounds__(256, 2) void qkv_gemm_kernel(
    const float* __restrict__ x,
    const float* __restrict__ Wq, const float* __restrict__ bq,
    const float* __restrict__ Wk, const float* __restrict__ bk,
    const float* __restrict__ Wv, const float* __restrict__ bv)
{
    __shared__ __align__(16) float As[16][132];
    __shared__ __align__(16) ull   Bsd[16 * 130];

    const float* W; const float* bias; float* out;
    int z = blockIdx.z;
    if (z == 0)      { W = Wq; bias = bq; out = g_q; }
    else if (z == 1) { W = Wk; bias = bk; out = g_k; }
    else             { W = Wv; bias = bv; out = g_v; }

    int m0 = blockIdx.y * 128;
    int n0 = blockIdx.x * 128;
    int tid = threadIdx.x;
    int tx = tid & 15, ty = tid >> 4;
    int r0 = ty * 8;

    ull acc[4][8];
#pragma unroll
    for (int i = 0; i < 4; i++)
#pragma unroll
        for (int j = 0; j < 8; j++) acc[i][j] = 0ULL;

    int lrow = tid >> 2;
    int lk   = (tid & 3) * 4;

    const float* pa0 = x + (size_t)(m0 + lrow)      * 512 + lk;
    const float* pa1 = x + (size_t)(m0 + lrow + 64) * 512 + lk;
    const float* pb0 = W + (size_t)(n0 + lrow)      * 512 + lk;
    const float* pb1 = W + (size_t)(n0 + lrow + 64) * 512 + lk;

    float4 a0 = *(const float4*)(pa0);
    float4 a1 = *(const float4*)(pa1);
    float4 b0 = *(const float4*)(pb0);
    float4 b1 = *(const float4*)(pb1);

    for (int k0 = 0; k0 < 512; k0 += 16) {
        __syncthreads();
        As[lk+0][lrow] = a0.x; As[lk+1][lrow] = a0.y; As[lk+2][lrow] = a0.z; As[lk+3][lrow] = a0.w;
        As[lk+0][lrow+64] = a1.x; As[lk+1][lrow+64] = a1.y; As[lk+2][lrow+64] = a1.z; As[lk+3][lrow+64] = a1.w;
        Bsd[(lk+0)*130 + lrow] = pack2(b0.x);
        Bsd[(lk+1)*130 + lrow] = pack2(b0.y);
        Bsd[(lk+2)*130 + lrow] = pack2(b0.z);
        Bsd[(lk+3)*130 + lrow] = pack2(b0.w);
        Bsd[(lk+0)*130 + lrow+64] = pack2(b1.x);
        Bsd[(lk+1)*130 + lrow+64] = pack2(b1.y);
        Bsd[(lk+2)*130 + lrow+64] = pack2(b1.z);
        Bsd[(lk+3)*130 + lrow+64] = pack2(b1.w);
        __syncthreads();
        if (k0 + 16 < 512) {
            a0 = *(const float4*)(pa0 + k0 + 16);
            a1 = *(const float4*)(pa1 + k0 + 16);
            b0 = *(const float4*)(pb0 + k0 + 16);
            b1 = *(const float4*)(pb1 + k0 + 16);
        }
#pragma unroll
        for (int kk = 0; kk < 16; kk++) {
            ulonglong2 ap0 = *(const ulonglong2*)&As[kk][r0];
            ulonglong2 ap1 = *(const ulonglong2*)&As[kk][r0 + 4];
            ulonglong2 bb0 = *(const ulonglong2*)&Bsd[kk*130 + 2*tx];
            ulonglong2 bb1 = *(const ulonglong2*)&Bsd[kk*130 + 2*tx + 32];
            ulonglong2 bb2 = *(const ulonglong2*)&Bsd[kk*130 + 2*tx + 64];
            ulonglong2 bb3 = *(const ulonglong2*)&Bsd[kk*130 + 2*tx + 96];
            ull a2[4] = {ap0.x, ap0.y, ap1.x, ap1.y};
            ull b2[8] = {bb0.x, bb0.y, bb1.x, bb1.y, bb2.x, bb2.y, bb3.x, bb3.y};
#pragma unroll
            for (int i = 0; i < 4; i++)
#pragma unroll
                for (int j = 0; j < 8; j++) fma2(acc[i][j], a2[i], b2[j]);
        }
    }

    float2 bias2[4];
#pragma unroll
    for (int jj = 0; jj < 4; jj++)
        bias2[jj] = *(const float2*)(bias + n0 + 2*tx + 32*jj);

#pragma unroll
    for (int i = 0; i < 4; i++) {
#pragma unroll
        for (int half = 0; half < 2; half++) {
            int m = m0 + r0 + 2 * i + half;
            int bb = m >> 11;
            int s  = m & 2047;
#pragma unroll
            for (int jj = 0; jj < 4; jj++) {
                int n = n0 + 2*tx + 32*jj;
                int h = n >> 6, c = n & 63;
                float2 o;
                if (half == 0) {
                    o.x = lo32(acc[i][2*jj])   + bias2[jj].x;
                    o.y = lo32(acc[i][2*jj+1]) + bias2[jj].y;
                } else {
                    o.x = hi32(acc[i][2*jj])   + bias2[jj].x;
                    o.y = hi32(acc[i][2*jj+1]) + bias2[jj].y;
                }
                *(float2*)(out + ((size_t)(bb * Hq + h) * Sq + s) * DKq + c) = o;
            }
        }
    }
}

// ---------------- Kernel B: L2-normalize q and k rows (over dk=64) ----------
__global__ __launch_bounds__(256) void normalize_kernel()
{
    int gw   = blockIdx.x * 8 + (threadIdx.x >> 5);
    int lane = threadIdx.x & 31;
    float* p;
    if (gw < BHq * Sq) p = g_k + (size_t)gw * 64;
    else               p = g_q + (size_t)(gw - BHq * Sq) * 64;
    float v0 = p[lane], v1 = p[lane + 32];
    float ss = v0 * v0 + v1 * v1;
#pragma unroll
    for (int o = 16; o; o >>= 1) ss += __shfl_xor_sync(0xffffffffu, ss, o);
    float inv = 1.0f / fmaxf(sqrtf(ss), EPSN);
    p[lane] = v0 * inv; p[lane + 32] = v1 * inv;
}

// ---------------- Kernel C: fused sim GEMM + ReLU + streaming top-9 ---------
// grid (S/128, BH); 256 threads; 2 blocks/SM; B dup'd + swizzled; pipelined.
__global__ __launch_bounds__(256, 2) void sim_topk_kernel()
{
    extern __shared__ __align__(16) float sm[];
    float* As  = sm;                    // 64*128 floats = 32KB
    ull*   Bsd = (ull*)(sm + 8192);     // 64*64 ull     = 32KB
    float* Ss  = sm + 16384;            // 128*68 floats = 34816B

    int bh = blockIdx.y;
    int i0 = blockIdx.x * 128;
    int tid = threadIdx.x;
    int tx = tid & 15, ty = tid >> 4;
    int r0 = ty * 8, c0 = 2 * tx;

    const float* kbase = g_k + (size_t)bh * Sq * DKq;
    const float* qbase = g_q + (size_t)bh * Sq * DKq;

    // fill As (kn tile, transposed + swizzled <<3), once
#pragma unroll
    for (int p = 0; p < 8; p++) {
        int f = tid + 256 * p;
        int r = f >> 4, dq = (f & 15) * 4;
        float4 v = *(const float4*)(kbase + (size_t)(i0 + r) * 64 + dq);
        int pr = r ^ (((dq >> 2) & 7) << 3);
        As[(dq + 0) * 128 + pr] = v.x;
        As[(dq + 1) * 128 + pr] = v.y;
        As[(dq + 2) * 128 + pr] = v.z;
        As[(dq + 3) * 128 + pr] = v.w;
    }

    float tv[9]; int ti[9];
#pragma unroll
    for (int q = 0; q < 9; q++) { tv[q] = -1.0f; ti[q] = 0; }

    int row = tid >> 1, part = tid & 1;
    int brow = tid >> 4, bdq = (tid & 15) * 4;
    const float* bptr = qbase + (size_t)brow * 64 + bdq;
    int sB = ((bdq >> 2) & 7) << 1;     // store swizzle for Bsd (bits 1-3 of col)

    // prefetch first Bs tile
    float4 br[4];
#pragma unroll
    for (int p = 0; p < 4; p++)
        br[p] = *(const float4*)(bptr + (size_t)(16 * p) * 64);

    for (int j0 = 0; j0 < Sq; j0 += 64) {
        __syncthreads();
        // store staged B tile: duplicated ulonglongs, transposed + swizzled
#pragma unroll
        for (int p = 0; p < 4; p++) {
            int jp = (brow + 16 * p) ^ sB;
            Bsd[(bdq + 0) * 64 + jp] = pack2(br[p].x);
            Bsd[(bdq + 1) * 64 + jp] = pack2(br[p].y);
            Bsd[(bdq + 2) * 64 + jp] = pack2(br[p].z);
            Bsd[(bdq + 3) * 64 + jp] = pack2(br[p].w);
        }
        __syncthreads();
        // prefetch next B tile
        if (j0 + 64 < Sq) {
#pragma unroll
            for (int p = 0; p < 4; p++)
                br[p] = *(const float4*)(bptr + (size_t)(j0 + 64 + 16 * p) * 64);
        }

        ull acc[4][4];
#pragma unroll
        for (int i = 0; i < 4; i++)
#pragma unroll
            for (int j = 0; j < 4; j++) acc[i][j] = 0ULL;

#pragma unroll 4
        for (int kk = 0; kk < 64; kk++) {
            int swzA = ((kk >> 2) & 7) << 3;
            int swzB = ((kk >> 2) & 7) << 1;
            ulonglong2 ap0 = *(const ulonglong2*)&As[kk * 128 + (r0 ^ swzA)];
            ulonglong2 ap1 = *(const ulonglong2*)&As[kk * 128 + (r0 ^ swzA) + 4];
            ulonglong2 bb0 = *(const ulonglong2*)&Bsd[kk * 64 + (c0 ^ swzB)];
            ulonglong2 bb1 = *(const ulonglong2*)&Bsd[kk * 64 + ((c0 + 32) ^ swzB)];
            ull a2[4] = {ap0.x, ap0.y, ap1.x, ap1.y};
            ull b2[4] = {bb0.x, bb0.y, bb1.x, bb1.y};
#pragma unroll
            for (int i = 0; i < 4; i++)
#pragma unroll
                for (int j = 0; j < 4; j++) fma2(acc[i][j], a2[i], b2[j]);
        }

        // write ReLU'd tile: rows (r0+2p, r0+2p+1), col pairs (c0, c0+32)
#pragma unroll
        for (int p = 0; p < 4; p++) {
            float2 w0L, w0H, w1L, w1H;
            w0L.x = fmaxf(lo32(acc[p][0]), 0.0f);
            w0L.y = fmaxf(lo32(acc[p][1]), 0.0f);
            w0H.x = fmaxf(hi32(acc[p][0]), 0.0f);
            w0H.y = fmaxf(hi32(acc[p][1]), 0.0f);
            w1L.x = fmaxf(lo32(acc[p][2]), 0.0f);
            w1L.y = fmaxf(lo32(acc[p][3]), 0.0f);
            w1H.x = fmaxf(hi32(acc[p][2]), 0.0f);
            w1H.y = fmaxf(hi32(acc[p][3]), 0.0f);
            *(float2*)&Ss[(r0 + 2*p)     * 68 + c0]      = w0L;
            *(float2*)&Ss[(r0 + 2*p + 1) * 68 + c0]      = w0H;
            *(float2*)&Ss[(r0 + 2*p)     * 68 + c0 + 32] = w1L;
            *(float2*)&Ss[(r0 + 2*p + 1) * 68 + c0 + 32] = w1H;
        }
        __syncthreads();

        // streaming top-9: this thread covers cols [part*32, part*32+32)
#pragma unroll
        for (int t = 0; t < 8; t++) {
            float4 v4 = *(const float4*)&Ss[row * 68 + part * 32 + t * 4];
            int cb = j0 + part * 32 + t * 4;
            float vv[4] = {v4.x, v4.y, v4.z, v4.w};
#pragma unroll
            for (int u = 0; u < 4; u++) {
                float v = vv[u];
                if (v > tv[8]) {
                    tv[8] = v; ti[8] = cb + u;
#pragma unroll
                    for (int q = 8; q > 0; q--) {
                        if (tv[q] > tv[q - 1]) {
                            float tf = tv[q]; tv[q] = tv[q - 1]; tv[q - 1] = tf;
                            int tt = ti[q]; ti[q] = ti[q - 1]; ti[q - 1] = tt;
                        }
                    }
                }
            }
        }
    }
    __syncthreads();

    // merge 2 per-row lists (alias As region)
    float* Mv = sm;                      // 256*9 floats
    int*   Mi = (int*)(sm + 2304);       // 256*9 ints
#pragma unroll
    for (int q = 0; q < 9; q++) {
        Mv[(row * 2 + part) * 9 + q] = tv[q];
        Mi[(row * 2 + part) * 9 + q] = ti[q];
    }
    __syncthreads();
    if (tid < 128) {
        int p0 = 0, p1 = 0;
        const float* L0v = Mv + (tid * 2) * 9;
        const float* L1v = Mv + (tid * 2 + 1) * 9;
        const int*   L0i = Mi + (tid * 2) * 9;
        const int*   L1i = Mi + (tid * 2 + 1) * 9;
        int obase = (bh * Sq + i0 + tid) * KN;
#pragma unroll
        for (int kk = 0; kk < KN; kk++) {
            float v0 = L0v[p0], v1 = L1v[p1];
            int ix0 = L0i[p0], ix1 = L1i[p1];
            bool take0 = (v0 > v1) || (v0 == v1 && ix0 < ix1);
            g_idx[obase + kk] = take0 ? ix0 : ix1;
            if (take0) p0++; else p1++;
        }
    }
}

// ---------------- prep: transpose conv_w [o][c][kk] -> Wt[kk][c][o] ---------
__global__ void transpose_convw_kernel(const float* __restrict__ w)
{
    int t = blockIdx.x * 256 + threadIdx.x;
    if (t < KN * DKq * DKq) {
        int o = t & 63, c = (t >> 6) & 63, kk = t >> 12;
        g_wt[t] = w[(o * 64 + c) * KN + kk];
    }
}

// ---------------- Kernel D: gather v by idx + grouped conv, scatter to y^T --
// grid (S/32, BH); 128 threads; w_s kk-loop software-pipelined.
__global__ __launch_bounds__(128, 2) void conv_kernel(const float* __restrict__ convb)
{
    extern __shared__ float smd[];
    float* v_s  = smd;                   // [288][64]
    float* w_s  = smd + 288 * 64;        // [64 c][64 o]
    int*   sidx = (int*)(smd + 288 * 64 + 4096);  // [288]

    int bh = blockIdx.y;
    int i0 = blockIdx.x * 32;
    int b  = bh >> 3, h = bh & 7;
    int tid = threadIdx.x;

    for (int t = tid; t < 288; t += 128)
        sidx[t] = g_idx[(bh * Sq + i0 + t / KN) * KN + (t % KN)];

    // prefetch kk=0 weights while idx/gather in flight
    float4 wreg[8];
#pragma unroll
    for (int p = 0; p < 8; p++)
        wreg[p] = *(const float4*)(g_wt + (tid + 128 * p) * 4);

    __syncthreads();

    const float* vbase = g_v + (size_t)bh * Sq * DKq;
    for (int p = 0; p < 36; p++) {
        int f = tid + 128 * p;           // 4608 float4s total
        int r = f >> 4, fq = (f & 15) * 4;
        int j = sidx[r];
        float4 vv = *(const float4*)(vbase + (size_t)j * 64 + fq);
        *(float4*)&v_s[r * 64 + fq] = vv;
    }

    int og = tid & 15; int o0 = og * 4;
    int ig = tid >> 4;                    // 0..7 -> 4 i's each
    ull acc[4][2];
#pragma unroll
    for (int t = 0; t < 4; t++) { acc[t][0] = 0ULL; acc[t][1] = 0ULL; }

    for (int kk = 0; kk < KN; kk++) {
        __syncthreads();
#pragma unroll
        for (int p = 0; p < 8; p++)
            *(float4*)&w_s[(tid + 128 * p) * 4] = wreg[p];
        __syncthreads();
        if (kk + 1 < KN) {
#pragma unroll
            for (int p = 0; p < 8; p++)
                wreg[p] = *(const float4*)(g_wt + (kk + 1) * 4096 + (tid + 128 * p) * 4);
        }
#pragma unroll 4
        for (int c = 0; c < 64; c++) {
            ulonglong2 wp = *(const ulonglong2*)&w_s[c * 64 + o0];
#pragma unroll
            for (int t = 0; t < 4; t++) {
                ull v2 = pack2(v_s[(((ig * 4 + t) * KN) + kk) * 64 + c]);
                fma2(acc[t][0], v2, wp.x);
                fma2(acc[t][1], v2, wp.y);
            }
        }
    }

    float4 cb = *(const float4*)(convb + o0);
    int colbase = (h * 64 + (i0 >> 5)) * Mq + b * Sq;   // d' = i0/32 constant per block
#pragma unroll
    for (int t = 0; t < 4; t++) {
        int il = ig * 4 + t;
        int sp = ((i0 + il) & 31) * 64 + o0;            // s' = (i%32)*64 + o
        float4 o;
        o.x = lo32(acc[t][0]) + cb.x;
        o.y = hi32(acc[t][0]) + cb.y;
        o.z = lo32(acc[t][1]) + cb.z;
        o.w = hi32(acc[t][1]) + cb.w;
        *(float4*)&g_y[colbase + sp] = o;
    }
}

// ---------------- Kernel E: final = y @ Wo^T + b (A = g_y^T, column-major) --
__global__ __launch_bounds__(256, 2) void out_gemm_kernel(
    const float* __restrict__ Wo, const float* __restrict__ bo,
    float* __restrict__ outp)
{
    __shared__ __align__(16) float As[16][132];
    __shared__ __align__(16) ull   Bsd[16 * 130];

    int m0 = blockIdx.y * 128, n0 = blockIdx.x * 128;
    int tid = threadIdx.x, tx = tid & 15, ty = tid >> 4;
    int r0 = ty * 8;

    ull acc[4][8];
#pragma unroll
    for (int i = 0; i < 4; i++)
#pragma unroll
        for (int j = 0; j < 8; j++) acc[i][j] = 0ULL;

    int lrow = tid >> 2, lk = (tid & 3) * 4;
    int fk = tid >> 5, fm = tid & 31;

    const float* pa0 = g_y + (size_t)fk * Mq + m0 + fm * 4;
    const float* pa1 = g_y + (size_t)(fk + 8) * Mq + m0 + fm * 4;
    const float* pb0 = Wo + (size_t)(n0 + lrow)      * 512 + lk;
    const float* pb1 = Wo + (size_t)(n0 + lrow + 64) * 512 + lk;

    float4 a0 = *(const float4*)(pa0);
    float4 a1 = *(const float4*)(pa1);
    float4 b0 = *(const float4*)(pb0);
    float4 b1 = *(const float4*)(pb1);

    for (int k0 = 0; k0 < 512; k0 += 16) {
        __syncthreads();
        *(float4*)&As[fk][fm * 4]     = a0;
        *(float4*)&As[fk + 8][fm * 4] = a1;
        Bsd[(lk+0)*130 + lrow] = pack2(b0.x);
        Bsd[(lk+1)*130 + lrow] = pack2(b0.y);
        Bsd[(lk+2)*130 + lrow] = pack2(b0.z);
        Bsd[(lk+3)*130 + lrow] = pack2(b0.w);
        Bsd[(lk+0)*130 + lrow+64] = pack2(b1.x);
        Bsd[(lk+1)*130 + lrow+64] = pack2(b1.y);
        Bsd[(lk+2)*130 + lrow+64] = pack2(b1.z);
        Bsd[(lk+3)*130 + lrow+64] = pack2(b1.w);
        __syncthreads();
        if (k0 + 16 < 512) {
            a0 = *(const float4*)(pa0 + (size_t)(k0 + 16) * Mq);
            a1 = *(const float4*)(pa1 + (size_t)(k0 + 16) * Mq);
            b0 = *(const float4*)(pb0 + k0 + 16);
            b1 = *(const float4*)(pb1 + k0 + 16);
        }
#pragma unroll
        for (int kk = 0; kk < 16; kk++) {
            ulonglong2 ap0 = *(const ulonglong2*)&As[kk][r0];
            ulonglong2 ap1 = *(const ulonglong2*)&As[kk][r0 + 4];
            ulonglong2 bb0 = *(const ulonglong2*)&Bsd[kk*130 + 2*tx];
            ulonglong2 bb1 = *(const ulonglong2*)&Bsd[kk*130 + 2*tx + 32];
            ulonglong2 bb2 = *(const ulonglong2*)&Bsd[kk*130 + 2*tx + 64];
            ulonglong2 bb3 = *(const ulonglong2*)&Bsd[kk*130 + 2*tx + 96];
            ull a2[4] = {ap0.x, ap0.y, ap1.x, ap1.y};
            ull b2[8] = {bb0.x, bb0.y, bb1.x, bb1.y, bb2.x, bb2.y, bb3.x, bb3.y};
#pragma unroll
            for (int i = 0; i < 4; i++)
#pragma unroll
                for (int j = 0; j < 8; j++) fma2(acc[i][j], a2[i], b2[j]);
        }
    }

    float2 bias2[4];
#pragma unroll
    for (int jj = 0; jj < 4; jj++)
        bias2[jj] = *(const float2*)(bo + n0 + 2*tx + 32*jj);

#pragma unroll
    for (int i = 0; i < 4; i++) {
#pragma unroll
        for (int half = 0; half < 2; half++) {
            int m = m0 + r0 + 2 * i + half;
            float* po = outp + (size_t)m * 512 + n0 + 2*tx;
#pragma unroll
            for (int jj = 0; jj < 4; jj++) {
                float2 o;
                if (half == 0) {
                    o.x = lo32(acc[i][2*jj])   + bias2[jj].x;
                    o.y = lo32(acc[i][2*jj+1]) + bias2[jj].y;
                } else {
                    o.x = hi32(acc[i][2*jj])   + bias2[jj].x;
                    o.y = hi32(acc[i][2*jj+1]) + bias2[jj].y;
                }
                *(float2*)(po + 32*jj) = o;
            }
        }
    }
}

// ---------------- launch -----------------------------------------------------
extern "C" void kernel_launch(void* const* d_in, const int* in_sizes, int n_in,
                              void* d_out, int out_size)
{
    (void)in_sizes; (void)n_in; (void)out_size;
    const float* x      = (const float*)d_in[0];
    const float* Wq_w   = (const float*)d_in[1];
    const float* Wq_b   = (const float*)d_in[2];
    const float* Wk_w   = (const float*)d_in[3];
    const float* Wk_b   = (const float*)d_in[4];
    const float* Wv_w   = (const float*)d_in[5];
    const float* Wv_b   = (const float*)d_in[6];
    const float* Wo_w   = (const float*)d_in[7];
    const float* Wo_b   = (const float*)d_in[8];
    const float* conv_w = (const float*)d_in[9];
    const float* conv_b = (const float*)d_in[10];
    float* outp = (float*)d_out;

    const int SMEM_C = (8192 + 8192 + 128 * 68) * 4;         // 100352 B
    const int SMEM_D = (288 * 64 + 64 * 64) * 4 + 288 * 4;   // 91264 B
    cudaFuncSetAttribute(sim_topk_kernel, cudaFuncAttributeMaxDynamicSharedMemorySize, SMEM_C);
    cudaFuncSetAttribute(conv_kernel,     cudaFuncAttributeMaxDynamicSharedMemorySize, SMEM_D);

    qkv_gemm_kernel<<<dim3(4, 64, 3), 256>>>(x, Wq_w, Wq_b, Wk_w, Wk_b, Wv_w, Wv_b);
    normalize_kernel<<<16384, 256>>>();
    transpose_convw_kernel<<<144, 256>>>(conv_w);
    sim_topk_kernel<<<dim3(16, 32), 256, SMEM_C>>>();
    conv_kernel<<<dim3(64, 32), 128, SMEM_D>>>(conv_b);
    out_gemm_kernel<<<dim3(4, 64), 256>>>(Wo_w, Wo_b, outp);
}